// round 16
// baseline (speedup 1.0000x reference)
#include <cuda_runtime.h>
#include <cuda_bf16.h>
#include <cuda_fp16.h>
#include <cstdint>
#include <math.h>

// ============================================================================
// EnsembleRatioModel — round 15: 64x64 warp tile (4 warps / 128 threads per
// CTA, 2 CTAs/SM). Cuts smem fragment bytes per HMMA 1.5x (192B -> 128B),
// flipping the mainloop from smem-bound to tensor-bound.
// Precision frozen at R11; compaction + z-batching + per-class pipeline depth
// retained from R14.
//
// Output packing (validated): [N*512) repr_ ; [3N) r*m ; [3N) s*m ; [3N) m
// ============================================================================

#define GN 131072

__device__ unsigned short g_X16[GN * 64];             // fp16 relu(x)
__device__ unsigned short g_A[GN * 512];              // fp16 trunk act ping
__device__ unsigned short g_B[3ULL * GN * 512];       // trunk pong (slice 0) + SW0 outs
__device__ float          g_fC[3ULL * GN * 256];      // SW1 raw fp32 outs
__device__ unsigned short g_whi[1736704];             // all weights, fp16 hi
__device__ unsigned short g_wlo[557056];              // trunk weights fp16 lo only

__device__ int g_cnt[4];
__device__ int g_cntpad[4];
__device__ int g_idx[3 * (GN + 128)];

#define IDX_STRIDE (GN + 128)

#define OFF_W0   0u
#define OFF_W1   32768u
#define OFF_W2   294912u
#define OFF_SW0  557056u      /* + p*262144 */
#define OFF_SW1  1343488u     /* + p*131072 */

// ---------------- helpers ----------------------------------------------------
__device__ __forceinline__ uint32_t smem_u32(const void* p) {
    uint32_t a;
    asm("{ .reg .u64 t; cvta.to.shared.u64 t, %1; cvt.u32.u64 %0, t; }"
        : "=r"(a) : "l"(p));
    return a;
}
__device__ __forceinline__ void cpasync16(uint32_t dst, const void* src) {
    asm volatile("cp.async.cg.shared.global [%0], [%1], 16;"
                 :: "r"(dst), "l"(src) : "memory");
}
template<int N>
__device__ __forceinline__ void wait_group_n() {
    asm volatile("cp.async.wait_group %0;" :: "n"(N) : "memory");
}
__device__ __forceinline__ void ldsm_x4(uint32_t* r, uint32_t addr) {
    asm volatile("ldmatrix.sync.aligned.m8n8.x4.shared.b16 {%0,%1,%2,%3}, [%4];"
                 : "=r"(r[0]), "=r"(r[1]), "=r"(r[2]), "=r"(r[3]) : "r"(addr));
}
__device__ __forceinline__ void mma_f16(float* d, const uint32_t* a,
                                        const uint32_t* b) {
    asm volatile(
        "mma.sync.aligned.m16n8k16.row.col.f32.f16.f16.f32 "
        "{%0,%1,%2,%3}, {%4,%5,%6,%7}, {%8,%9}, {%0,%1,%2,%3};"
        : "+f"(d[0]), "+f"(d[1]), "+f"(d[2]), "+f"(d[3])
        : "r"(a[0]), "r"(a[1]), "r"(a[2]), "r"(a[3]), "r"(b[0]), "r"(b[1]));
}
__device__ __forceinline__ void split_fp16(float v, __half& h, __half& l) {
    h = __float2half_rn(v);
    l = __float2half_rn(v - __half2float(h));
}

// ============================================================================
// GEMM template. TERMS: 2 = A.(Whi+Wlo) [2-stage], 1 = A.Whi [3-stage].
// OMODE: 1 = fp16 single out (+opt fp32 raw); 2 = fp32 raw out only.
// 128x128 CTA tile, 128 thr (4 warps), warp tile 64x64, K-chunk 64.
// ============================================================================
#define ROW_PITCH  144
#define COMP_BYTES 18432      /* 128 * 144 */

template<int TERMS, int OMODE>
__global__ void __launch_bounds__(128, 2)
gemm_mma(const unsigned short* __restrict__ A16, size_t a_ps,
         const unsigned short* __restrict__ Whi, const unsigned short* __restrict__ Wlo,
         size_t w_ps,
         const float* __restrict__ bias, size_t b_ps,
         float* __restrict__ raw_out, size_t r_ps,
         unsigned short* __restrict__ O16, size_t o_ps,
         int K, int Ntot, int write_raw,
         const int* __restrict__ row_idx_base, const int* __restrict__ cnt_base)
{
    constexpr int NS = (TERMS == 2) ? 2 : 3;           // pipeline stages
    constexpr uint32_t STAGE = (TERMS + 1) * COMP_BYTES;
    extern __shared__ __align__(16) char smem[];
    const uint32_t smem_base = smem_u32(smem);

    const int p  = blockIdx.z;
    const int m0 = blockIdx.y * 128;
    if (cnt_base && m0 >= __ldg(cnt_base + p)) return;
    const int n0 = blockIdx.x * 128;

    const int* row_idx = row_idx_base ? row_idx_base + (size_t)p * IDX_STRIDE : nullptr;
    A16 += (size_t)p * a_ps;
    Whi += (size_t)p * w_ps;
    Wlo += (size_t)p * w_ps;
    bias += (size_t)p * b_ps;
    raw_out += (size_t)p * r_ps;
    O16 += (size_t)p * o_ps;

    const int tid   = threadIdx.x;
    const int wid   = tid >> 5;
    const int lane  = tid & 31;
    const int g     = lane >> 2;
    const int tk    = lane & 3;
    const int warpM = wid >> 1;        // 0..1 -> 64-row half
    const int warpN = wid & 1;         // 0..1 -> 64-col half

    const int nk = K >> 6;             // K-chunks of 64

    const uint32_t a_lrow = (uint32_t)(lane & 15) * ROW_PITCH + (uint32_t)(lane >> 4) * 16;
    const uint32_t b_lrow = (uint32_t)((lane & 7) + ((lane >> 4) << 3)) * ROW_PITCH
                          + (uint32_t)((lane >> 3) & 1) * 16;

    auto load_chunk = [&](int c, int s) {
        const uint32_t st = smem_base + (uint32_t)s * STAGE;
        const int koff = c * 64;
        constexpr int NITER = (TERMS + 1) * 8;
#pragma unroll
        for (int i = 0; i < NITER; i++) {
            int idx  = i * 128 + tid;
            int comp = idx >> 10;           // 0:A 1:Whi 2:Wlo
            int rem  = idx & 1023;
            int row  = rem >> 3;
            int seg  = rem & 7;
            uint32_t dst = st + (uint32_t)comp * COMP_BYTES
                         + (uint32_t)row * ROW_PITCH + (uint32_t)seg * 16;
            const unsigned short* src;
            size_t roff;
            if (comp == 0) {
                int gr = m0 + row;
                if (row_idx) gr = __ldg(&row_idx[gr]);
                src = A16;
                roff = (size_t)gr * K;
            } else if (comp == 1) { src = Whi; roff = (size_t)(n0 + row) * K; }
            else                  { src = Wlo; roff = (size_t)(n0 + row) * K; }
            cpasync16(dst, src + roff + koff + seg * 8);
        }
        asm volatile("cp.async.commit_group;" ::: "memory");
    };

    float acc[4][8][4];
#pragma unroll
    for (int i = 0; i < 4; i++)
#pragma unroll
        for (int j = 0; j < 8; j++)
#pragma unroll
            for (int r = 0; r < 4; r++) acc[i][j][r] = 0.f;

    // prologue: fill NS-1 stages
    load_chunk(0, 0);
    if (NS >= 3 && nk > 1) load_chunk(1, 1);

    for (int c = 0; c < nk; c++) {
        const int cn = c + NS - 1;
        if (cn < nk) {
            load_chunk(cn, cn % NS);
            wait_group_n<NS - 1>();
        } else {
            const int rem = nk - 1 - c;
            if (NS >= 3 && rem == 1) wait_group_n<1>();
            else                     wait_group_n<0>();
        }
        __syncthreads();

        const uint32_t sb = smem_base + (uint32_t)(c % NS) * STAGE;
        const uint32_t aBase = sb + (uint32_t)(warpM * 64) * ROW_PITCH;
        const uint32_t bBase = sb + COMP_BYTES + (uint32_t)(warpN * 64) * ROW_PITCH;

#pragma unroll
        for (int t = 0; t < 4; t++) {
            const uint32_t kb = (uint32_t)t * 32;

            // B hi fragments: 4 x ldsm_x4 -> 8 n8-tiles (64 cols)
            uint32_t bh[8][2];
#pragma unroll
            for (int jj = 0; jj < 4; jj++) {
                uint32_t r4[4];
                uint32_t addr = bBase + (uint32_t)(jj * 16) * ROW_PITCH + kb + b_lrow;
                ldsm_x4(r4, addr);
                bh[jj * 2][0] = r4[0]; bh[jj * 2][1] = r4[1];
                bh[jj * 2 + 1][0] = r4[2]; bh[jj * 2 + 1][1] = r4[3];
            }
            // A fragments: 4 x ldsm_x4 (64 rows)
            uint32_t ah[4][4];
#pragma unroll
            for (int i = 0; i < 4; i++)
                ldsm_x4(ah[i], aBase + (uint32_t)(i * 16) * ROW_PITCH + kb + a_lrow);

#pragma unroll
            for (int i = 0; i < 4; i++)
#pragma unroll
                for (int j = 0; j < 8; j++)
                    mma_f16(acc[i][j], ah[i], bh[j]);

            if (TERMS == 2) {
                uint32_t bl[8][2];
#pragma unroll
                for (int jj = 0; jj < 4; jj++) {
                    uint32_t r4[4];
                    uint32_t addr = bBase + COMP_BYTES + (uint32_t)(jj * 16) * ROW_PITCH + kb + b_lrow;
                    ldsm_x4(r4, addr);
                    bl[jj * 2][0] = r4[0]; bl[jj * 2][1] = r4[1];
                    bl[jj * 2 + 1][0] = r4[2]; bl[jj * 2 + 1][1] = r4[3];
                }
#pragma unroll
                for (int i = 0; i < 4; i++)
#pragma unroll
                    for (int j = 0; j < 8; j++)
                        mma_f16(acc[i][j], ah[i], bl[j]);
            }
        }
        __syncthreads();
    }

    // ---- epilogue ----------------------------------------------------------
#pragma unroll
    for (int j = 0; j < 8; j++) {
        const int cc = n0 + warpN * 64 + j * 8 + tk * 2;
        const float b0v = bias[cc];
        const float b1v = bias[cc + 1];
#pragma unroll
        for (int i = 0; i < 4; i++) {
            const int r0 = m0 + warpM * 64 + i * 16 + g;
#pragma unroll
            for (int half = 0; half < 2; half++) {
                const int r = r0 + half * 8;
                float v0 = acc[i][j][half * 2 + 0] + b0v;
                float v1 = acc[i][j][half * 2 + 1] + b1v;
                const size_t off = (size_t)r * Ntot + cc;
                if (OMODE == 2) {
                    *(float2*)(raw_out + off) = make_float2(v0, v1);
                } else {
                    if (write_raw)
                        *(float2*)(raw_out + off) = make_float2(v0, v1);
                    __half h0 = __float2half_rn(fmaxf(v0, 0.f));
                    __half h1 = __float2half_rn(fmaxf(v1, 0.f));
                    uint32_t hp = (uint32_t)__half_as_ushort(h0)
                                | ((uint32_t)__half_as_ushort(h1) << 16);
                    *(uint32_t*)(O16 + off) = hp;
                }
            }
        }
    }
}

// ---- prep: relu(x) -> fp16 --------------------------------------------------
__global__ void prep_x(const float* __restrict__ src,
                       unsigned short* __restrict__ o, int n)
{
    int t = blockIdx.x * blockDim.x + threadIdx.x;
    if (t >= n) return;
    o[t] = __half_as_ushort(__float2half_rn(fmaxf(src[t], 0.0f)));
}

// ---- prep: ALL weights transpose (+split for trunk) -------------------------
__global__ void prep_all(const float* __restrict__ W0, const float* __restrict__ W1,
                         const float* __restrict__ W2, const float* __restrict__ SW0,
                         const float* __restrict__ SW1,
                         unsigned short* __restrict__ hi, unsigned short* __restrict__ lo)
{
    int t = blockIdx.x * blockDim.x + threadIdx.x;
    if (t >= 1736704) return;
    const float* src;
    int local, Kd, Nd;
    unsigned int dbase;
    bool trunk = false;
    if (t < 294912) {
        trunk = true;
        if (t < 32768) { src = W0; local = t; Kd = 64; Nd = 512; dbase = OFF_W0; }
        else           { src = W1; local = t - 32768; Kd = 512; Nd = 512; dbase = OFF_W1; }
    } else if (t < 557056) {
        trunk = true;
        src = W2; local = t - 294912; Kd = 512; Nd = 512; dbase = OFF_W2;
    } else if (t < 1343488) {
        int u = t - 557056;
        int p = u / 262144;
        local = u - p * 262144;
        src = SW0 + (size_t)p * 262144; Kd = 512; Nd = 512;
        dbase = OFF_SW0 + (unsigned int)p * 262144u;
    } else {
        int u = t - 1343488;
        int p = u / 131072;
        local = u - p * 131072;
        src = SW1 + (size_t)p * 131072; Kd = 512; Nd = 256;
        dbase = OFF_SW1 + (unsigned int)p * 131072u;
    }
    int k = local / Nd, n = local % Nd;
    float v = src[local];
    size_t d = (size_t)dbase + (size_t)n * Kd + k;
    if (trunk) {
        __half h, l;
        split_fp16(v, h, l);
        hi[d] = __half_as_ushort(h);
        lo[d] = __half_as_ushort(l);
    } else {
        hi[d] = __half_as_ushort(__float2half_rn(v));
    }
}

// ---- index build (g_cnt zeroed via cudaMemsetAsync host-side) ---------------
__global__ void idx_build(const int* __restrict__ y, const int* __restrict__ pairs, int n)
{
    int t = blockIdx.x * blockDim.x + threadIdx.x;
    if (t >= n) return;
    int yv = y[t];
#pragma unroll
    for (int p = 0; p < 3; p++) {
        if (yv == pairs[2 * p] || yv == pairs[2 * p + 1]) {
            int pos = atomicAdd(&g_cnt[p], 1);
            g_idx[p * IDX_STRIDE + pos] = t;
        }
    }
}
__global__ void idx_pad()
{
    int p = blockIdx.x;
    int c = g_cnt[p];
    int cp = (c + 127) & ~127;
    for (int i = c + threadIdx.x; i < cp; i += 128)
        g_idx[p * IDX_STRIDE + i] = 0;
    if (threadIdx.x == 0) g_cntpad[p] = cp;
}

// ---- final (z-batched): fp32 packed rows, scatter to original index ---------
__global__ void subnet_final(const float* __restrict__ fC_base,
                             const float* __restrict__ SW2,
                             const float* __restrict__ Sb2,
                             const int*   __restrict__ idx_base,
                             const int*   __restrict__ cnt_base,
                             float* __restrict__ out_r,
                             float* __restrict__ out_s,
                             float* __restrict__ out_m)
{
    const int p = blockIdx.z;
    const float* fC = fC_base + (size_t)p * GN * 256;
    const int* idxlist = idx_base + (size_t)p * IDX_STRIDE;
    float* r_out = out_r + (size_t)p * GN;
    float* s_out = out_s + (size_t)p * GN;
    float* m_out = out_m + (size_t)p * GN;

    __shared__ float w[256];
    const int tid = threadIdx.x;
    w[tid] = SW2[p * 256 + tid];
    __syncthreads();

    const float sb = Sb2[p];
    const int limit = __ldg(cnt_base + p);

    const int lane = tid & 31;
    const int warp = tid >> 5;
    const int gw = blockIdx.x * (blockDim.x >> 5) + warp;
    const int warps_total = gridDim.x * (blockDim.x >> 5);

    for (int n = gw; n < limit; n += warps_total) {
        const size_t base = (size_t)n * 256;
        float acc = 0.f;
#pragma unroll
        for (int j = 0; j < 8; j++) {
            int c = lane + 32 * j;
            acc += fmaxf(fC[base + c], 0.f) * w[c];
        }
#pragma unroll
        for (int o = 16; o > 0; o >>= 1)
            acc += __shfl_xor_sync(0xFFFFFFFFu, acc, o);

        if (lane == 0) {
            float logit = acc + sb;
            float s = 1.f / (1.f + expf(-logit));
            s = fmaxf(s, 1e-9f);
            float r = (1.f - s) / s;
            int orig = __ldg(&idxlist[n]);
            r_out[orig] = r;
            s_out[orig] = s;
            m_out[orig] = 1.f;
        }
    }
}

// ============================================================================
extern "C" void kernel_launch(void* const* d_in, const int* in_sizes, int n_in,
                              void* d_out, int out_size)
{
    const float* x     = (const float*)d_in[0];
    const int*   y     = (const int*)  d_in[1];
    const int*   pairs = (const int*)  d_in[2];
    const float* W0    = (const float*)d_in[3];
    const float* b0    = (const float*)d_in[4];
    const float* W1    = (const float*)d_in[5];
    const float* b1    = (const float*)d_in[6];
    const float* W2    = (const float*)d_in[7];
    const float* b2    = (const float*)d_in[8];
    const float* SW0   = (const float*)d_in[9];
    const float* Sb0   = (const float*)d_in[10];
    const float* SW1   = (const float*)d_in[11];
    const float* Sb1   = (const float*)d_in[12];
    const float* SW2   = (const float*)d_in[13];
    const float* Sb2   = (const float*)d_in[14];

    const int M = GN;
    float* out   = (float*)d_out;
    float* repr  = out;
    float* r_seg = out + (size_t)M * 512;
    float* s_seg = r_seg + 3 * (size_t)M;
    float* m_seg = s_seg + 3 * (size_t)M;

    unsigned short *X16, *A, *B, *whi, *wlo;
    float *fC;
    cudaGetSymbolAddress((void**)&X16, g_X16);
    cudaGetSymbolAddress((void**)&A,   g_A);
    cudaGetSymbolAddress((void**)&B,   g_B);
    cudaGetSymbolAddress((void**)&fC,  g_fC);
    cudaGetSymbolAddress((void**)&whi, g_whi);
    cudaGetSymbolAddress((void**)&wlo, g_wlo);
    int *idxp, *cntp, *cntpadp;
    cudaGetSymbolAddress((void**)&idxp, g_idx);
    cudaGetSymbolAddress((void**)&cntp, g_cnt);
    cudaGetSymbolAddress((void**)&cntpadp, g_cntpad);

    const size_t sh2 = 2 * 3 * COMP_BYTES;   // trunk: 2 stages x 3 comps = 110592
    const size_t sh1 = 3 * 2 * COMP_BYTES;   // subnet: 3 stages x 2 comps = 110592

    cudaFuncSetAttribute((const void*)gemm_mma<2,1>,
        cudaFuncAttributeMaxDynamicSharedMemorySize, (int)sh2);
    cudaFuncSetAttribute((const void*)gemm_mma<1,1>,
        cudaFuncAttributeMaxDynamicSharedMemorySize, (int)sh1);
    cudaFuncSetAttribute((const void*)gemm_mma<1,2>,
        cudaFuncAttributeMaxDynamicSharedMemorySize, (int)sh1);

    dim3 blk(128);

    cudaMemsetAsync(cntp, 0, 4 * sizeof(int));
    prep_x<<<(M * 64 + 255) / 256, 256>>>(x, X16, M * 64);
    prep_all<<<(1736704 + 255) / 256, 256>>>(W0, W1, W2, SW0, SW1, whi, wlo);
    idx_build<<<(M + 255) / 256, 256>>>(y, pairs, M);

    // trunk: 2-term fp16, 2-stage
    gemm_mma<2,1><<<dim3(4, M / 128, 1), blk, sh2>>>(
        X16, 0, whi + OFF_W0, wlo + OFF_W0, 0, b0, 0,
        nullptr, 0, A, 0, 64, 512, 0, nullptr, nullptr);
    gemm_mma<2,1><<<dim3(4, M / 128, 1), blk, sh2>>>(
        A, 0, whi + OFF_W1, wlo + OFF_W1, 0, b1, 0,
        nullptr, 0, B, 0, 512, 512, 0, nullptr, nullptr);
    gemm_mma<2,1><<<dim3(4, M / 128, 1), blk, sh2>>>(
        B, 0, whi + OFF_W2, wlo + OFF_W2, 0, b2, 0,
        repr, 0, A, 0, 512, 512, 1, nullptr, nullptr);

    idx_pad<<<3, 128>>>();

    // SW0: 1-term fp16, 3-stage, z-batched, gathered rows
    gemm_mma<1,1><<<dim3(4, M / 128, 3), blk, sh1>>>(
        A, 0, whi + OFF_SW0, whi + OFF_SW0, 262144, Sb0, 512,
        nullptr, 0, B, (size_t)GN * 512,
        512, 512, 0, idxp, cntpadp);

    // SW1: 1-term fp16, 3-stage, z-batched, fp32 raw outputs
    gemm_mma<1,2><<<dim3(2, M / 128, 3), blk, sh1>>>(
        B, (size_t)GN * 512, whi + OFF_SW1, whi + OFF_SW1, 131072, Sb1, 256,
        fC, (size_t)GN * 256, nullptr, 0,
        512, 256, 0, nullptr, cntpadp);

    // zero subnet output segments (must precede final's scatter)
    cudaMemsetAsync(r_seg, 0, 9 * (size_t)M * sizeof(float));

    // final
    subnet_final<<<dim3(512, 1, 3), dim3(256)>>>(
        fC, SW2, Sb2, idxp, cntp, r_seg, s_seg, m_seg);
}

// round 17
// speedup vs baseline: 1.0888x; 1.0888x over previous
#include <cuda_runtime.h>
#include <cuda_bf16.h>
#include <cuda_fp16.h>
#include <cstdint>
#include <math.h>

// ============================================================================
// EnsembleRatioModel — round 16: R13 GEMM config (64x32 warp tile, 256 thr,
// 2 CTAs/SM) + SW1 epilogue fused with the final 256->1 dot (268MB fC write +
// 268MB read collapse to 3MB of per-row partials). Deterministic reductions.
//
// Output packing (validated): [N*512) repr_ ; [3N) r*m ; [3N) s*m ; [3N) m
// ============================================================================

#define GN 131072

__device__ unsigned short g_X16[GN * 64];             // fp16 relu(x)
__device__ unsigned short g_A[GN * 512];              // fp16 trunk act ping
__device__ unsigned short g_B[3ULL * GN * 512];       // trunk pong (slice 0) + SW0 outs
__device__ float          g_part[2ULL * 3 * GN];      // SW1 fused-dot partials
__device__ unsigned short g_whi[1736704];             // all weights, fp16 hi
__device__ unsigned short g_wlo[557056];              // trunk weights fp16 lo only

__device__ int g_cnt[4];
__device__ int g_cntpad[4];
__device__ int g_idx[3 * (GN + 128)];

#define IDX_STRIDE (GN + 128)

#define OFF_W0   0u
#define OFF_W1   32768u
#define OFF_W2   294912u
#define OFF_SW0  557056u      /* + p*262144 */
#define OFF_SW1  1343488u     /* + p*131072 */

// ---------------- helpers ----------------------------------------------------
__device__ __forceinline__ uint32_t smem_u32(const void* p) {
    uint32_t a;
    asm("{ .reg .u64 t; cvta.to.shared.u64 t, %1; cvt.u32.u64 %0, t; }"
        : "=r"(a) : "l"(p));
    return a;
}
__device__ __forceinline__ void cpasync16(uint32_t dst, const void* src) {
    asm volatile("cp.async.cg.shared.global [%0], [%1], 16;"
                 :: "r"(dst), "l"(src) : "memory");
}
__device__ __forceinline__ void ldsm_x4(uint32_t* r, uint32_t addr) {
    asm volatile("ldmatrix.sync.aligned.m8n8.x4.shared.b16 {%0,%1,%2,%3}, [%4];"
                 : "=r"(r[0]), "=r"(r[1]), "=r"(r[2]), "=r"(r[3]) : "r"(addr));
}
__device__ __forceinline__ void mma_f16(float* d, const uint32_t* a,
                                        const uint32_t* b) {
    asm volatile(
        "mma.sync.aligned.m16n8k16.row.col.f32.f16.f16.f32 "
        "{%0,%1,%2,%3}, {%4,%5,%6,%7}, {%8,%9}, {%0,%1,%2,%3};"
        : "+f"(d[0]), "+f"(d[1]), "+f"(d[2]), "+f"(d[3])
        : "r"(a[0]), "r"(a[1]), "r"(a[2]), "r"(a[3]), "r"(b[0]), "r"(b[1]));
}
__device__ __forceinline__ void split_fp16(float v, __half& h, __half& l) {
    h = __float2half_rn(v);
    l = __float2half_rn(v - __half2float(h));
}

// ============================================================================
// GEMM template. TERMS: 2 = A.(Whi+Wlo), 1 = A.Whi.
// OMODE: 1 = fp16 single out (+opt fp32 raw); 3 = fused final-dot epilogue.
// 128x128 CTA tile, 256 thr, warp 64x32, K-chunk 64, double buffer.
// ============================================================================
#define ROW_PITCH  144
#define COMP_BYTES 18432      /* 128 * 144 */

template<int TERMS, int OMODE>
__global__ void __launch_bounds__(256, 2)
gemm_mma(const unsigned short* __restrict__ A16, size_t a_ps,
         const unsigned short* __restrict__ Whi, const unsigned short* __restrict__ Wlo,
         size_t w_ps,
         const float* __restrict__ bias, size_t b_ps,
         float* __restrict__ raw_out, size_t r_ps,
         unsigned short* __restrict__ O16, size_t o_ps,
         int K, int Ntot, int write_raw,
         const int* __restrict__ row_idx_base, const int* __restrict__ cnt_base,
         const float* __restrict__ sw2base, float* __restrict__ part_out)
{
    constexpr uint32_t STAGE = (TERMS + 1) * COMP_BYTES;
    extern __shared__ __align__(16) char smem[];
    const uint32_t smem_base = smem_u32(smem);

    const int p  = blockIdx.z;
    const int m0 = blockIdx.y * 128;
    if (cnt_base && m0 >= __ldg(cnt_base + p)) return;
    const int n0 = blockIdx.x * 128;

    const int* row_idx = row_idx_base ? row_idx_base + (size_t)p * IDX_STRIDE : nullptr;
    A16 += (size_t)p * a_ps;
    Whi += (size_t)p * w_ps;
    Wlo += (size_t)p * w_ps;
    bias += (size_t)p * b_ps;
    raw_out += (size_t)p * r_ps;
    O16 += (size_t)p * o_ps;
    const float* sw2 = sw2base ? sw2base + p * 256 : nullptr;

    const int tid   = threadIdx.x;
    const int wid   = tid >> 5;
    const int lane  = tid & 31;
    const int g     = lane >> 2;
    const int tk    = lane & 3;
    const int warpM = wid >> 2;
    const int warpN = wid & 3;

    const int nk = K >> 6;     // K-chunks of 64

    const uint32_t a_lrow = (uint32_t)(lane & 15) * ROW_PITCH + (uint32_t)(lane >> 4) * 16;
    const uint32_t b_lrow = (uint32_t)((lane & 7) + ((lane >> 4) << 3)) * ROW_PITCH
                          + (uint32_t)((lane >> 3) & 1) * 16;

    auto load_chunk = [&](int c, int s) {
        const uint32_t st = smem_base + (uint32_t)s * STAGE;
        const int koff = c * 64;
        constexpr int NITER = (TERMS == 2) ? 12 : 8;
#pragma unroll
        for (int i = 0; i < NITER; i++) {
            int idx  = i * 256 + tid;
            int comp = idx >> 10;           // 0:A 1:Whi 2:Wlo
            int rem  = idx & 1023;
            int row  = rem >> 3;
            int seg  = rem & 7;
            uint32_t dst = st + (uint32_t)comp * COMP_BYTES
                         + (uint32_t)row * ROW_PITCH + (uint32_t)seg * 16;
            const unsigned short* src;
            size_t roff;
            if (comp == 0) {
                int gr = m0 + row;
                if (row_idx) gr = __ldg(&row_idx[gr]);
                src = A16;
                roff = (size_t)gr * K;
            } else if (comp == 1) { src = Whi; roff = (size_t)(n0 + row) * K; }
            else                  { src = Wlo; roff = (size_t)(n0 + row) * K; }
            cpasync16(dst, src + roff + koff + seg * 8);
        }
        asm volatile("cp.async.commit_group;" ::: "memory");
    };

    float acc[4][4][4];
#pragma unroll
    for (int i = 0; i < 4; i++)
#pragma unroll
        for (int j = 0; j < 4; j++)
#pragma unroll
            for (int r = 0; r < 4; r++) acc[i][j][r] = 0.f;

    load_chunk(0, 0);

    for (int c = 0; c < nk; c++) {
        if (c + 1 < nk) {
            load_chunk(c + 1, (c + 1) & 1);
            asm volatile("cp.async.wait_group 1;" ::: "memory");
        } else {
            asm volatile("cp.async.wait_group 0;" ::: "memory");
        }
        __syncthreads();

        const uint32_t sb = smem_base + (uint32_t)(c & 1) * STAGE;
        const uint32_t aBase = sb + (uint32_t)(warpM * 64) * ROW_PITCH;
        const uint32_t bBase = sb + COMP_BYTES + (uint32_t)(warpN * 32) * ROW_PITCH;

#pragma unroll
        for (int t = 0; t < 4; t++) {
            const uint32_t kb = (uint32_t)t * 32;

            uint32_t bh[4][2];
#pragma unroll
            for (int jj = 0; jj < 2; jj++) {
                uint32_t r4[4];
                uint32_t addr = bBase + (uint32_t)(jj * 16) * ROW_PITCH + kb + b_lrow;
                ldsm_x4(r4, addr);
                bh[jj * 2][0] = r4[0]; bh[jj * 2][1] = r4[1];
                bh[jj * 2 + 1][0] = r4[2]; bh[jj * 2 + 1][1] = r4[3];
            }
            uint32_t ah[4][4];
#pragma unroll
            for (int i = 0; i < 4; i++)
                ldsm_x4(ah[i], aBase + (uint32_t)(i * 16) * ROW_PITCH + kb + a_lrow);

#pragma unroll
            for (int i = 0; i < 4; i++)
#pragma unroll
                for (int j = 0; j < 4; j++)
                    mma_f16(acc[i][j], ah[i], bh[j]);

            if (TERMS == 2) {
                uint32_t bl[4][2];
#pragma unroll
                for (int jj = 0; jj < 2; jj++) {
                    uint32_t r4[4];
                    uint32_t addr = bBase + COMP_BYTES + (uint32_t)(jj * 16) * ROW_PITCH + kb + b_lrow;
                    ldsm_x4(r4, addr);
                    bl[jj * 2][0] = r4[0]; bl[jj * 2][1] = r4[1];
                    bl[jj * 2 + 1][0] = r4[2]; bl[jj * 2 + 1][1] = r4[3];
                }
#pragma unroll
                for (int i = 0; i < 4; i++)
#pragma unroll
                    for (int j = 0; j < 4; j++)
                        mma_f16(acc[i][j], ah[i], bl[j]);
            }
        }
        __syncthreads();
    }

    if (OMODE == 3) {
        // ---- fused final-dot epilogue: partial = sum_cols relu(v)*sw2 ------
        float part[4][2];
#pragma unroll
        for (int i = 0; i < 4; i++) { part[i][0] = 0.f; part[i][1] = 0.f; }
#pragma unroll
        for (int j = 0; j < 4; j++) {
            const int cc = n0 + warpN * 32 + j * 8 + tk * 2;
            const float b0v = bias[cc];
            const float b1v = bias[cc + 1];
            const float w0 = sw2[cc];
            const float w1 = sw2[cc + 1];
#pragma unroll
            for (int i = 0; i < 4; i++) {
#pragma unroll
                for (int half = 0; half < 2; half++) {
                    float v0 = acc[i][j][half * 2 + 0] + b0v;
                    float v1 = acc[i][j][half * 2 + 1] + b1v;
                    part[i][half] += fmaxf(v0, 0.f) * w0 + fmaxf(v1, 0.f) * w1;
                }
            }
        }
#pragma unroll
        for (int o = 1; o < 4; o <<= 1)
#pragma unroll
            for (int i = 0; i < 4; i++) {
                part[i][0] += __shfl_xor_sync(0xFFFFFFFFu, part[i][0], o);
                part[i][1] += __shfl_xor_sync(0xFFFFFFFFu, part[i][1], o);
            }
        __syncthreads();                 // stage smem now reusable
        float* red = (float*)smem;       // [128 rows][4 warpN]
        if (tk == 0) {
#pragma unroll
            for (int i = 0; i < 4; i++)
#pragma unroll
                for (int half = 0; half < 2; half++) {
                    int row = warpM * 64 + i * 16 + g + half * 8;
                    red[row * 4 + warpN] = part[i][half];
                }
        }
        __syncthreads();
        if (tid < 128) {
            float s = red[tid * 4 + 0] + red[tid * 4 + 1]
                    + red[tid * 4 + 2] + red[tid * 4 + 3];
            part_out[((size_t)(n0 >> 7) * 3 + p) * GN + m0 + tid] = s;
        }
        return;
    }

    // ---- standard epilogue (OMODE == 1) --------------------------------------
#pragma unroll
    for (int j = 0; j < 4; j++) {
        const int cc = n0 + warpN * 32 + j * 8 + tk * 2;
        const float b0v = bias[cc];
        const float b1v = bias[cc + 1];
#pragma unroll
        for (int i = 0; i < 4; i++) {
            const int r0 = m0 + warpM * 64 + i * 16 + g;
#pragma unroll
            for (int half = 0; half < 2; half++) {
                const int r = r0 + half * 8;
                float v0 = acc[i][j][half * 2 + 0] + b0v;
                float v1 = acc[i][j][half * 2 + 1] + b1v;
                const size_t off = (size_t)r * Ntot + cc;
                if (write_raw)
                    *(float2*)(raw_out + off) = make_float2(v0, v1);
                __half h0 = __float2half_rn(fmaxf(v0, 0.f));
                __half h1 = __float2half_rn(fmaxf(v1, 0.f));
                uint32_t hp = (uint32_t)__half_as_ushort(h0)
                            | ((uint32_t)__half_as_ushort(h1) << 16);
                *(uint32_t*)(O16 + off) = hp;
            }
        }
    }
}

// ---- prep: relu(x) -> fp16 --------------------------------------------------
__global__ void prep_x(const float* __restrict__ src,
                       unsigned short* __restrict__ o, int n)
{
    int t = blockIdx.x * blockDim.x + threadIdx.x;
    if (t >= n) return;
    o[t] = __half_as_ushort(__float2half_rn(fmaxf(src[t], 0.0f)));
}

// ---- prep: ALL weights transpose (+split for trunk) -------------------------
__global__ void prep_all(const float* __restrict__ W0, const float* __restrict__ W1,
                         const float* __restrict__ W2, const float* __restrict__ SW0,
                         const float* __restrict__ SW1,
                         unsigned short* __restrict__ hi, unsigned short* __restrict__ lo)
{
    int t = blockIdx.x * blockDim.x + threadIdx.x;
    if (t >= 1736704) return;
    const float* src;
    int local, Kd, Nd;
    unsigned int dbase;
    bool trunk = false;
    if (t < 294912) {
        trunk = true;
        if (t < 32768) { src = W0; local = t; Kd = 64; Nd = 512; dbase = OFF_W0; }
        else           { src = W1; local = t - 32768; Kd = 512; Nd = 512; dbase = OFF_W1; }
    } else if (t < 557056) {
        trunk = true;
        src = W2; local = t - 294912; Kd = 512; Nd = 512; dbase = OFF_W2;
    } else if (t < 1343488) {
        int u = t - 557056;
        int p = u / 262144;
        local = u - p * 262144;
        src = SW0 + (size_t)p * 262144; Kd = 512; Nd = 512;
        dbase = OFF_SW0 + (unsigned int)p * 262144u;
    } else {
        int u = t - 1343488;
        int p = u / 131072;
        local = u - p * 131072;
        src = SW1 + (size_t)p * 131072; Kd = 512; Nd = 256;
        dbase = OFF_SW1 + (unsigned int)p * 131072u;
    }
    int k = local / Nd, n = local % Nd;
    float v = src[local];
    size_t d = (size_t)dbase + (size_t)n * Kd + k;
    if (trunk) {
        __half h, l;
        split_fp16(v, h, l);
        hi[d] = __half_as_ushort(h);
        lo[d] = __half_as_ushort(l);
    } else {
        hi[d] = __half_as_ushort(__float2half_rn(v));
    }
}

// ---- index build (g_cnt zeroed via cudaMemsetAsync host-side) ---------------
__global__ void idx_build(const int* __restrict__ y, const int* __restrict__ pairs, int n)
{
    int t = blockIdx.x * blockDim.x + threadIdx.x;
    if (t >= n) return;
    int yv = y[t];
#pragma unroll
    for (int p = 0; p < 3; p++) {
        if (yv == pairs[2 * p] || yv == pairs[2 * p + 1]) {
            int pos = atomicAdd(&g_cnt[p], 1);
            g_idx[p * IDX_STRIDE + pos] = t;
        }
    }
}
__global__ void idx_pad()
{
    int p = blockIdx.x;
    int c = g_cnt[p];
    int cp = (c + 127) & ~127;
    for (int i = c + threadIdx.x; i < cp; i += 128)
        g_idx[p * IDX_STRIDE + i] = 0;
    if (threadIdx.x == 0) g_cntpad[p] = cp;
}

// ---- final (fused partials): logit = part0 + part1 + Sb2; scatter ----------
__global__ void final_fused(const float* __restrict__ part,
                            const float* __restrict__ Sb2,
                            const int*   __restrict__ idx_base,
                            const int*   __restrict__ cnt_base,
                            float* __restrict__ out_r,
                            float* __restrict__ out_s,
                            float* __restrict__ out_m)
{
    const int p = blockIdx.z;
    const int* idxlist = idx_base + (size_t)p * IDX_STRIDE;
    float* r_out = out_r + (size_t)p * GN;
    float* s_out = out_s + (size_t)p * GN;
    float* m_out = out_m + (size_t)p * GN;
    const float sb = Sb2[p];
    const int limit = __ldg(cnt_base + p);

    for (int n = blockIdx.x * blockDim.x + threadIdx.x; n < limit;
         n += gridDim.x * blockDim.x) {
        float logit = part[(size_t)p * GN + n]
                    + part[(size_t)(3 + p) * GN + n] + sb;
        float s = 1.f / (1.f + expf(-logit));
        s = fmaxf(s, 1e-9f);
        float r = (1.f - s) / s;
        int orig = __ldg(&idxlist[n]);
        r_out[orig] = r;
        s_out[orig] = s;
        m_out[orig] = 1.f;
    }
}

// ============================================================================
extern "C" void kernel_launch(void* const* d_in, const int* in_sizes, int n_in,
                              void* d_out, int out_size)
{
    const float* x     = (const float*)d_in[0];
    const int*   y     = (const int*)  d_in[1];
    const int*   pairs = (const int*)  d_in[2];
    const float* W0    = (const float*)d_in[3];
    const float* b0    = (const float*)d_in[4];
    const float* W1    = (const float*)d_in[5];
    const float* b1    = (const float*)d_in[6];
    const float* W2    = (const float*)d_in[7];
    const float* b2    = (const float*)d_in[8];
    const float* SW0   = (const float*)d_in[9];
    const float* Sb0   = (const float*)d_in[10];
    const float* SW1   = (const float*)d_in[11];
    const float* Sb1   = (const float*)d_in[12];
    const float* SW2   = (const float*)d_in[13];
    const float* Sb2   = (const float*)d_in[14];

    const int M = GN;
    float* out   = (float*)d_out;
    float* repr  = out;
    float* r_seg = out + (size_t)M * 512;
    float* s_seg = r_seg + 3 * (size_t)M;
    float* m_seg = s_seg + 3 * (size_t)M;

    unsigned short *X16, *A, *B, *whi, *wlo;
    float *partp;
    cudaGetSymbolAddress((void**)&X16, g_X16);
    cudaGetSymbolAddress((void**)&A,   g_A);
    cudaGetSymbolAddress((void**)&B,   g_B);
    cudaGetSymbolAddress((void**)&partp, g_part);
    cudaGetSymbolAddress((void**)&whi, g_whi);
    cudaGetSymbolAddress((void**)&wlo, g_wlo);
    int *idxp, *cntp, *cntpadp;
    cudaGetSymbolAddress((void**)&idxp, g_idx);
    cudaGetSymbolAddress((void**)&cntp, g_cnt);
    cudaGetSymbolAddress((void**)&cntpadp, g_cntpad);

    const size_t sh2 = 2 * 3 * COMP_BYTES;
    const size_t sh1 = 2 * 2 * COMP_BYTES;

    cudaFuncSetAttribute((const void*)gemm_mma<2,1>,
        cudaFuncAttributeMaxDynamicSharedMemorySize, (int)sh2);
    cudaFuncSetAttribute((const void*)gemm_mma<1,1>,
        cudaFuncAttributeMaxDynamicSharedMemorySize, (int)sh1);
    cudaFuncSetAttribute((const void*)gemm_mma<1,3>,
        cudaFuncAttributeMaxDynamicSharedMemorySize, (int)sh1);

    dim3 blk(256);

    cudaMemsetAsync(cntp, 0, 4 * sizeof(int));
    prep_x<<<(M * 64 + 255) / 256, 256>>>(x, X16, M * 64);
    prep_all<<<(1736704 + 255) / 256, 256>>>(W0, W1, W2, SW0, SW1, whi, wlo);
    idx_build<<<(M + 255) / 256, 256>>>(y, pairs, M);

    // trunk: 2-term fp16 (A single x W hi/lo), 2-stage
    gemm_mma<2,1><<<dim3(4, M / 128, 1), blk, sh2>>>(
        X16, 0, whi + OFF_W0, wlo + OFF_W0, 0, b0, 0,
        nullptr, 0, A, 0, 64, 512, 0, nullptr, nullptr, nullptr, nullptr);
    gemm_mma<2,1><<<dim3(4, M / 128, 1), blk, sh2>>>(
        A, 0, whi + OFF_W1, wlo + OFF_W1, 0, b1, 0,
        nullptr, 0, B, 0, 512, 512, 0, nullptr, nullptr, nullptr, nullptr);
    gemm_mma<2,1><<<dim3(4, M / 128, 1), blk, sh2>>>(
        B, 0, whi + OFF_W2, wlo + OFF_W2, 0, b2, 0,
        repr, 0, A, 0, 512, 512, 1, nullptr, nullptr, nullptr, nullptr);

    idx_pad<<<3, 128>>>();

    // SW0: 1-term fp16, z-batched, gathered rows
    gemm_mma<1,1><<<dim3(4, M / 128, 3), blk, sh1>>>(
        A, 0, whi + OFF_SW0, whi + OFF_SW0, 262144, Sb0, 512,
        nullptr, 0, B, (size_t)GN * 512,
        512, 512, 0, idxp, cntpadp, nullptr, nullptr);

    // SW1: 1-term fp16, fused final-dot epilogue (writes per-row partials)
    gemm_mma<1,3><<<dim3(2, M / 128, 3), blk, sh1>>>(
        B, (size_t)GN * 512, whi + OFF_SW1, whi + OFF_SW1, 131072, Sb1, 256,
        nullptr, 0, nullptr, 0,
        512, 256, 0, nullptr, cntpadp, SW2, partp);

    cudaMemsetAsync(r_seg, 0, 9 * (size_t)M * sizeof(float));

    // final: sum 2 partials, sigmoid, scatter
    final_fused<<<dim3(512, 1, 3), dim3(256)>>>(
        partp, Sb2, idxp, cntp, r_seg, s_seg, m_seg);
}